// round 11
// baseline (speedup 1.0000x reference)
#include <cuda_runtime.h>

#define IMG 256
#define TW 64
#define TH 32
#define PR (TH + 6)   // 38 quartet-plane rows

typedef unsigned long long u64;

// ---- packed f32x2 helpers (sm_103a FFMA2 path, PTX-only) ----
__device__ __forceinline__ u64 pk2(float lo, float hi) {
    u64 r; asm("mov.b64 %0, {%1,%2};" : "=l"(r) : "f"(lo), "f"(hi)); return r;
}
__device__ __forceinline__ void upk2(float& lo, float& hi, u64 p) {
    asm("mov.b64 {%0,%1}, %2;" : "=f"(lo), "=f"(hi) : "l"(p));
}
__device__ __forceinline__ u64 f2fma(u64 a, u64 b, u64 c) {
    u64 d; asm("fma.rn.f32x2 %0,%1,%2,%3;" : "=l"(d) : "l"(a), "l"(b), "l"(c)); return d;
}
__device__ __forceinline__ u64 f2mul(u64 a, u64 b) {
    u64 d; asm("mul.rn.f32x2 %0,%1,%2;" : "=l"(d) : "l"(a), "l"(b)); return d;
}
__device__ __forceinline__ u64 f2add(u64 a, u64 b) {
    u64 d; asm("add.rn.f32x2 %0,%1,%2;" : "=l"(d) : "l"(a), "l"(b)); return d;
}
__device__ __forceinline__ float ex2f(float x) {
    float r; asm("ex2.approx.f32 %0, %1;" : "=f"(r) : "f"(x)); return r;
}
__device__ __forceinline__ float rcpf(float x) {
    float r; asm("rcp.approx.f32 %0, %1;" : "=f"(r) : "f"(x)); return r;
}

__device__ __forceinline__ int reflect(int v) {
    v = (v < 0) ? -v : v;
    return (v > IMG - 1) ? 2 * (IMG - 1) - v : v;
}

__global__ __launch_bounds__(256, 4)
void AdaptiveGaussianFilter_66675072303489_kernel(
    const float* __restrict__ x,
    const float* __restrict__ sigma,
    float* __restrict__ out)
{
    // Planar quartet planes: m=w0, a=w-1+w+1, b=w-2+w+2, c=w-3+w+3 (38.9 KB)
    __shared__ __align__(16) float qm[PR][TW];
    __shared__ __align__(16) float qa[PR][TW];
    __shared__ __align__(16) float qb[PR][TW];
    __shared__ __align__(16) float qc[PR][TW];

    const int ch = blockIdx.z;
    const int x0 = blockIdx.x * TW;
    const int y0 = blockIdx.y * TH;

    const float* xc = x     + (size_t)ch * IMG * IMG;
    const float* sc = sigma + (size_t)ch * IMG * IMG;
    float*       oc = out   + (size_t)ch * IMG * IMG;

    const int tx  = threadIdx.x;
    const int ty  = threadIdx.y;
    const int tid = ty * 32 + tx;

    const int c2  = tx << 1;                 // 0..62
    const int ly0 = ty << 2;                 // 0..28

    // Preload all 4 sigma pairs (latency hides under pass-1)
    const float* sp = sc + (y0 + ly0) * IMG + x0 + c2;
    u64 sg[4];
    sg[0] = *(const u64*)(sp);
    sg[1] = *(const u64*)(sp + IMG);
    sg[2] = *(const u64*)(sp + 2 * IMG);
    sg[3] = *(const u64*)(sp + 3 * IMG);

    // ---- Pass 1: 8-wide strips, vectorized LDG.128 on interior blocks ----
    // Strip (r, c0): covers plane row r, cols c0..c0+7; needs x cols c0-4..c0+11
    // (16 floats, first used at +1). 38 rows x 8 strips = 304 items.
    const bool interior = (blockIdx.x != 0) & (blockIdx.x != 3) &
                          (blockIdx.y != 0) & (blockIdx.y != 7);
    #pragma unroll
    for (int it = 0; it < 2; it++) {
        int idx = tid + it * 256;
        if (idx < PR * 8) {
            int r  = idx >> 3;
            int c0 = (idx & 7) << 3;
            float v[16];                     // x[x0+c0-4 .. x0+c0+11]
            if (interior) {
                const float4* src = (const float4*)(xc + (y0 + r - 3) * IMG + (x0 + c0 - 4));
                #pragma unroll
                for (int q = 0; q < 4; q++) {
                    float4 f = src[q];
                    v[4*q+0] = f.x; v[4*q+1] = f.y; v[4*q+2] = f.z; v[4*q+3] = f.w;
                }
            } else {
                const float* srow = xc + reflect(y0 + r - 3) * IMG;
                #pragma unroll
                for (int j = 0; j < 16; j++)
                    v[j] = srow[reflect(x0 + c0 - 4 + j)];
            }
            // combos for col c0+i (i=0..7): m=v[i+4], a=v[i+3]+v[i+5],
            //                               b=v[i+2]+v[i+6], c=v[i+1]+v[i+7]
            #pragma unroll
            for (int hv = 0; hv < 2; hv++) {
                const int i0 = hv * 4;
                *(float4*)&qm[r][c0 + i0] = make_float4(
                    v[i0+4], v[i0+5], v[i0+6], v[i0+7]);
                *(float4*)&qa[r][c0 + i0] = make_float4(
                    v[i0+3]+v[i0+5], v[i0+4]+v[i0+6], v[i0+5]+v[i0+7], v[i0+6]+v[i0+8]);
                *(float4*)&qb[r][c0 + i0] = make_float4(
                    v[i0+2]+v[i0+6], v[i0+3]+v[i0+7], v[i0+4]+v[i0+8], v[i0+5]+v[i0+9]);
                *(float4*)&qc[r][c0 + i0] = make_float4(
                    v[i0+1]+v[i0+7], v[i0+2]+v[i0+8], v[i0+3]+v[i0+9], v[i0+4]+v[i0+10]);
            }
        }
    }

    // ---- Exp chains for all 4 output rows BEFORE the barrier (MUFU hidden) ----
    const u64 NHL = pk2(-0.72134752f, -0.72134752f);   // -0.5*log2(e)
    u64 t[4], t4[4], t9[4];
    #pragma unroll
    for (int k = 0; k < 4; k++) {
        u64 z = f2mul(sg[k], sg[k]);
        z = f2mul(z, NHL);
        float zl, zh; upk2(zl, zh, z);
        t[k]  = pk2(ex2f(zl), ex2f(zh));
        u64 t2 = f2mul(t[k], t[k]);
        t4[k] = f2mul(t2, t2);
        t9[k] = f2mul(f2mul(t4[k], t4[k]), t[k]);
    }
    __syncthreads();

    // ---- Pass 2: stream 10 window rows; 4 packed accumulators ----
    u64 acc[4];
    #pragma unroll
    for (int w = -3; w <= 6; w++) {
        const int prow = ly0 + w + 3;        // 0..37
        const u64 qm_ = *(const u64*)&qm[prow][c2];
        const u64 qa_ = *(const u64*)&qa[prow][c2];
        const u64 qb_ = *(const u64*)&qb[prow][c2];
        const u64 qc_ = *(const u64*)&qc[prow][c2];
        #pragma unroll
        for (int k = 0; k < 4; k++) {
            const int d = (w > k) ? (w - k) : (k - w);
            if (d > 3) continue;
            u64 h = f2fma(t[k],  qa_, qm_);
            h     = f2fma(t4[k], qb_, h);
            h     = f2fma(t9[k], qc_, h);
            if (w == k - 3)     acc[k] = f2mul(t9[k], h);     // first contribution
            else if (d == 3)    acc[k] = f2fma(t9[k], h, acc[k]);
            else if (d == 2)    acc[k] = f2fma(t4[k], h, acc[k]);
            else if (d == 1)    acc[k] = f2fma(t[k],  h, acc[k]);
            else                acc[k] = f2add(acc[k], h);
        }
    }

    // ---- Epilogue: normalize and store ----
    const u64 TWO2 = pk2(2.0f, 2.0f);
    const u64 ONE2 = pk2(1.0f, 1.0f);
    float* op = oc + (y0 + ly0) * IMG + x0 + c2;
    #pragma unroll
    for (int k = 0; k < 4; k++) {
        u64 S  = f2fma(TWO2, f2add(f2add(t[k], t4[k]), t9[k]), ONE2);
        u64 SS = f2mul(S, S);
        float sl, sh; upk2(sl, sh, SS);
        float al, ah; upk2(al, ah, acc[k]);
        *(u64*)(op + k * IMG) = pk2(al * rcpf(sl), ah * rcpf(sh));
    }
}

extern "C" void kernel_launch(void* const* d_in, const int* in_sizes, int n_in,
                              void* d_out, int out_size)
{
    const float* x     = (const float*)d_in[0];
    const float* sigma = (const float*)d_in[1];
    float*       out   = (float*)d_out;

    dim3 block(32, 8, 1);
    dim3 grid(IMG / TW, IMG / TH, 16 * 3);   // 4 x 8 x 48 = 1536
    AdaptiveGaussianFilter_66675072303489_kernel<<<grid, block>>>(x, sigma, out);
}